// round 7
// baseline (speedup 1.0000x reference)
#include <cuda_runtime.h>
#include <cstdint>

// Problem constants: B=1, Z=1, X=Y=360, C=80, Np=1,993,728
#define XDIM  360
#define YDIM  360
#define CDIM  80
#define CELLS (XDIM * YDIM)          // 129600 = 8100 * 16
#define NP_MAX 2000000
#define SCAN_NB 127                  // ceil(129600/1024), <= 148 SMs (all resident)

__device__ __align__(256) int g_cell[NP_MAX];      // cell per point, -1 dropped
__device__ __align__(256) int g_count[CELLS];      // histogram (zeroed by gather)
__device__ __align__(256) int g_offset[CELLS];     // exclusive scan
__device__ __align__(256) int g_cursor[CELLS];     // reorder cursors
__device__ __align__(256) int g_pid[NP_MAX];       // point ids sorted by cell
__device__ int g_ready[SCAN_NB];                   // lookback flags (agg+1), zeroed by idx_hist

// ---------------------------------------------------------------------------
// 1) cell index + histogram. Also re-zeroes g_ready for this replay's scan.
// XLA rewrites (v-lo)/DX into (v-lo)*(1/DX) with rn-rounded f32 reciprocal —
// replicate exactly (validated: rel_err ~4e-8).
// ---------------------------------------------------------------------------
__global__ void idx_hist_kernel(const float* __restrict__ geom, int np) {
    if (blockIdx.x == 0 && threadIdx.x < SCAN_NB)
        g_ready[threadIdx.x] = 0;

    int p = blockIdx.x * blockDim.x + threadIdx.x;
    if (p >= np) return;

    float gx = geom[3 * (size_t)p + 0];
    float gy = geom[3 * (size_t)p + 1];
    float gz = geom[3 * (size_t)p + 2];

    const float lox = -53.85f - 0.3f * 0.5f;   // -54.0f in f32
    const float loz =   0.0f  - 20.0f * 0.5f;  // -10.0f
    const float rxy = 1.0f / 0.3f;             // rn f32 reciprocal
    const float rz  = 1.0f / 20.0f;            // exact

    int xi = (int)floorf((gx - lox) * rxy);
    int yi = (int)floorf((gy - lox) * rxy);
    int zi = (int)floorf((gz - loz) * rz);

    bool kept = (xi >= 0) & (xi < XDIM) & (yi >= 0) & (yi < YDIM) &
                (zi >= 0) & (zi < 1);
    int cell = kept ? (xi * YDIM + yi) : -1;
    g_cell[p] = cell;
    if (cell >= 0) atomicAdd(&g_count[cell], 1);
}

// ---------------------------------------------------------------------------
// 2) single-kernel exclusive scan with decoupled lookback.
// 127 blocks (all resident in wave 1 on 148 SMs): each does a local block scan,
// publishes (block_total + 1) to g_ready[b], then sums all predecessors'
// aggregates (no serial chain). g_ready pre-zeroed by idx_hist.
// ---------------------------------------------------------------------------
__global__ __launch_bounds__(1024) void scan_kernel() {
    __shared__ int warpsum[32];
    __shared__ int sbase;

    int t = threadIdx.x;
    int b = blockIdx.x;
    int gid = b * 1024 + t;
    int v = (gid < CELLS) ? g_count[gid] : 0;

    // local inclusive scan
    int x = v;
    #pragma unroll
    for (int d = 1; d < 32; d <<= 1) {
        int y = __shfl_up_sync(0xFFFFFFFFu, x, d);
        if ((t & 31) >= d) x += y;
    }
    if ((t & 31) == 31) warpsum[t >> 5] = x;
    __syncthreads();
    if (t < 32) {
        int w = warpsum[t];
        #pragma unroll
        for (int d = 1; d < 32; d <<= 1) {
            int y = __shfl_up_sync(0xFFFFFFFFu, w, d);
            if (t >= d) w += y;
        }
        warpsum[t] = w;
    }
    __syncthreads();
    int wbase = (t >= 32) ? warpsum[(t >> 5) - 1] : 0;
    int incl = x + wbase;

    // publish aggregate ASAP (thread 1023 holds the block total)
    if (t == 1023) {
        atomicExch(&g_ready[b], incl + 1);   // +1: distinguish from "not ready"
    }

    // warp 0 gathers predecessor aggregates
    if (t < 32) {
        int sum = 0;
        for (int j = t; j < b; j += 32) {
            int r;
            do { r = *(volatile int*)&g_ready[j]; } while (r == 0);
            sum += r - 1;
        }
        #pragma unroll
        for (int d = 16; d >= 1; d >>= 1)
            sum += __shfl_xor_sync(0xFFFFFFFFu, sum, d);
        if (t == 0) sbase = sum;
    }
    __syncthreads();

    if (gid < CELLS) {
        int o = incl - v + sbase;            // exclusive prefix
        g_offset[gid] = o;
        g_cursor[gid] = o;
    }
}

// ---------------------------------------------------------------------------
// 3) reorder: bucket point ids by cell
// ---------------------------------------------------------------------------
__global__ void reorder_kernel(int np) {
    int p = blockIdx.x * blockDim.x + threadIdx.x;
    if (p >= np) return;
    int cell = g_cell[p];
    if (cell < 0) return;
    int pos = atomicAdd(&g_cursor[cell], 1);
    g_pid[pos] = p;
}

// ---------------------------------------------------------------------------
// 4) gather: warp per cell; lanes 0..19 own one float4 of C=80.
//    Direct g_pid loads INSIDE the kernel (device symbol — never pass it as a
//    host-side launch arg, that passes the host shadow address!).
//    4-way unroll -> 4 independent feats LDG.128 in flight per warp.
//    512-thread blocks, min 3 blocks/SM -> 48 warps/SM latency hiding.
//    Epilogue transposes via smem, writes out[c][xy] coalesced, then zeroes
//    g_count for the next graph replay (deterministic). No float atomics.
// ---------------------------------------------------------------------------
__global__ __launch_bounds__(512, 3) void gather_kernel(
    const float* __restrict__ feats, float* __restrict__ out)
{
    __shared__ float s[16][81];   // [local cell][channel], stride 81

    int lane = threadIdx.x & 31;
    int wid  = threadIdx.x >> 5;            // local cell 0..15
    int cell = blockIdx.x * 16 + wid;       // CELLS = 8100*16 exact

    int start = g_offset[cell];
    int cnt   = g_count[cell];
    if (lane == 0) g_count[cell] = 0;       // reset for next replay

    const float4* __restrict__ f4 = reinterpret_cast<const float4*>(feats);
    const bool active = (lane < 20);
    float4 acc = make_float4(0.f, 0.f, 0.f, 0.f);

    int k = 0;
    for (; k + 4 <= cnt; k += 4) {
        int p0 = g_pid[start + k + 0];
        int p1 = g_pid[start + k + 1];
        int p2 = g_pid[start + k + 2];
        int p3 = g_pid[start + k + 3];
        if (active) {
            float4 v0 = __ldg(&f4[(size_t)p0 * 20 + lane]);
            float4 v1 = __ldg(&f4[(size_t)p1 * 20 + lane]);
            float4 v2 = __ldg(&f4[(size_t)p2 * 20 + lane]);
            float4 v3 = __ldg(&f4[(size_t)p3 * 20 + lane]);
            acc.x += v0.x; acc.y += v0.y; acc.z += v0.z; acc.w += v0.w;
            acc.x += v1.x; acc.y += v1.y; acc.z += v1.z; acc.w += v1.w;
            acc.x += v2.x; acc.y += v2.y; acc.z += v2.z; acc.w += v2.w;
            acc.x += v3.x; acc.y += v3.y; acc.z += v3.z; acc.w += v3.w;
        }
    }
    for (; k < cnt; k++) {
        int p0 = g_pid[start + k];
        if (active) {
            float4 v0 = __ldg(&f4[(size_t)p0 * 20 + lane]);
            acc.x += v0.x; acc.y += v0.y; acc.z += v0.z; acc.w += v0.w;
        }
    }

    if (active) {
        int c = 4 * lane;
        s[wid][c + 0] = acc.x;
        s[wid][c + 1] = acc.y;
        s[wid][c + 2] = acc.z;
        s[wid][c + 3] = acc.w;
    }
    __syncthreads();

    // write out: 80 c x 16 xy = 1280 floats; 16 consecutive xy per channel row
    int xy0 = blockIdx.x * 16;
    #pragma unroll
    for (int r = 0; r < 3; r++) {
        int linear = r * 512 + threadIdx.x;
        if (linear < CDIM * 16) {
            int c = linear >> 4;          // channel
            int x = linear & 15;          // local xy
            out[(size_t)c * CELLS + xy0 + x] = s[x][c];
        }
    }
}

// ---------------------------------------------------------------------------
// Launch (4 kernels)
// ---------------------------------------------------------------------------
extern "C" void kernel_launch(void* const* d_in, const int* in_sizes, int n_in,
                              void* d_out, int out_size)
{
    const float* geom  = (const float*)d_in[0];
    const float* feats = (const float*)d_in[1];
    float* out = (float*)d_out;

    int np = in_sizes[0] / 3;   // 1,993,728

    idx_hist_kernel<<<(np + 255) / 256, 256>>>(geom, np);
    scan_kernel<<<SCAN_NB, 1024>>>();
    reorder_kernel<<<(np + 255) / 256, 256>>>(np);
    gather_kernel<<<CELLS / 16, 512>>>(feats, out);
}